// round 12
// baseline (speedup 1.0000x reference)
#include <cuda_runtime.h>
#include <cuda_bf16.h>
#include <cstdint>

// ---------------------------------------------------------------------------
// Fused RV-linear layer (HMMA mma.sync path).
// R5..R12: x loads merged to one LDG.128 per (row-group, s) + xor1-bfly pair
//     exchange (halves x L1 wavefronts); B repacked for LDS.64 fragments.
// ---------------------------------------------------------------------------

#define NTHREADS 256
#define TILE_M   128

// ---- dynamic shared memory layout (bytes) ----
#define SM_QROW  0                 // 128 floats
#define SM_SPW   512               // 128 floats
#define SM_SPB   1024
#define SM_BMU   1536
#define SM_RED   2048              // 16 floats
#define SM_BH    2112              // 128*72 uint32 = 36864 B
#define SM_BL    (2112 + 36864)
#define SMEM_TOTAL (SM_BL + 36864) // 75840 B
#define BSTRIDE  72                // %32==8 -> two-phase conflict-free LDS.64

__device__ __forceinline__ uint32_t pack_bf16x2(float lo, float hi) {
    uint32_t r;
    asm("cvt.rn.bf16x2.f32 %0, %1, %2;" : "=r"(r) : "f"(hi), "f"(lo));
    return r;
}
__device__ __forceinline__ float bf_lo(uint32_t u) { return __uint_as_float(u << 16); }
__device__ __forceinline__ float bf_hi(uint32_t u) { return __uint_as_float(u & 0xffff0000u); }

__device__ __forceinline__ void mma16816(float* d, uint32_t a0, uint32_t a1,
                                         uint32_t a2, uint32_t a3,
                                         uint32_t b0, uint32_t b1) {
    asm volatile(
        "mma.sync.aligned.m16n8k16.row.col.f32.bf16.bf16.f32 "
        "{%0,%1,%2,%3}, {%4,%5,%6,%7}, {%8,%9}, {%0,%1,%2,%3};"
        : "+f"(d[0]), "+f"(d[1]), "+f"(d[2]), "+f"(d[3])
        : "r"(a0), "r"(a1), "r"(a2), "r"(a3), "r"(b0), "r"(b1));
}

// ---------------------------------------------------------------------------
__global__ void __launch_bounds__(NTHREADS, 2)
rvlinear_kernel(const float* __restrict__ x,
                const float* __restrict__ w_mu,
                const float* __restrict__ w_sigma,
                const float* __restrict__ b_mu,
                const float* __restrict__ b_sigma,
                float* __restrict__ out_mu,
                float* __restrict__ out_sigma,
                float* __restrict__ out_kl) {
    extern __shared__ __align__(16) char smem[];
    float*    qrow = (float*)(smem + SM_QROW);
    float*    spw  = (float*)(smem + SM_SPW);
    float*    spb  = (float*)(smem + SM_SPB);
    float*    bmu  = (float*)(smem + SM_BMU);
    float*    red  = (float*)(smem + SM_RED);
    uint32_t* Bh   = (uint32_t*)(smem + SM_BH);
    uint32_t* Bl   = (uint32_t*)(smem + SM_BL);

    const int tid  = threadIdx.x;
    const int warp = tid >> 5;
    const int lane = tid & 31;

    if (tid < 128) {
        spw[tid] = log1pf(expf(w_sigma[tid]));
        spb[tid] = log1pf(expf(b_sigma[tid]));
        bmu[tid] = b_mu[tid];
    }

    // ---- build B = w_mu^T as bf16x2 k-pair words, hi/lo, LDS.64 layout ----
    // word index for kpair p (p=0..63), col n:  n*BSTRIDE + (p>>3)*8 + 2*(p&3) + ((p>>2)&1)
    {
        const int nsub = lane & 7;                 // 0..7
        const int psub = lane >> 3;                // 0..3
        const int n4b  = nsub + 8 * (warp & 3);    // 0..31
        const int pb   = psub + 4 * (warp >> 2);   // 0..7
#pragma unroll
        for (int j = 0; j < 8; j++) {
            const int p  = pb + 8 * j;             // kpair 0..63
            const int n0 = 4 * n4b;
            const int wslot = (p >> 3) * 8 + 2 * (p & 3) + ((p >> 2) & 1);
            float4 w0 = *(const float4*)(w_mu + (2 * p) * 128 + n0);
            float4 w1 = *(const float4*)(w_mu + (2 * p + 1) * 128 + n0);
            float a[4] = {w0.x, w0.y, w0.z, w0.w};
            float b[4] = {w1.x, w1.y, w1.z, w1.w};
#pragma unroll
            for (int dn = 0; dn < 4; dn++) {
                uint32_t h = pack_bf16x2(a[dn], b[dn]);
                uint32_t l = pack_bf16x2(a[dn] - bf_lo(h), b[dn] - bf_hi(h));
                const int n = n0 + dn;
                Bh[n * BSTRIDE + wslot] = h;
                Bl[n * BSTRIDE + wslot] = l;
            }
        }
    }
    __syncthreads();

    // ---- main GEMM: 4x2 warp grid; warp tile = 32 rows x 64 cols ----
    const int wm = warp & 3;       // M group (32 rows)
    const int wn = warp >> 2;      // N half (64 cols)
    const int rb = blockIdx.x * TILE_M + wm * 32 + (lane >> 2);
    const float* xr = x + (size_t)rb * 128;
    const int j4 = lane & 3;
    const int g  = ((j4 & 1) << 1) | (j4 >> 1);   // load-slot permutation
    const bool oddj = (j4 & 1);

    float acc[2][8][4];
#pragma unroll
    for (int mt = 0; mt < 2; mt++)
#pragma unroll
        for (int t = 0; t < 8; t++) {
            acc[mt][t][0] = 0.f; acc[mt][t][1] = 0.f;
            acc[mt][t][2] = 0.f; acc[mt][t][3] = 0.f;
        }

    float q[4] = {0.f, 0.f, 0.f, 0.f};

    for (int s = 0; s < 8; s++) {
        const int cg = 16 * s + 4 * g;

        uint32_t ah[2][4], al[2][4];
#pragma unroll
        for (int o = 0; o < 4; o++) {
            float4 v = *(const float4*)(xr + (size_t)(8 * o) * 128 + cg);

            if (wn == 0) {
                float4 sp = *(const float4*)(spw + cg);
                q[o] += v.x * v.x * sp.x + v.y * v.y * sp.y
                      + v.z * v.z * sp.z + v.w * v.w * sp.w;
            }

            // split both loaded pairs to bf16 hi/lo
            uint32_t h0 = pack_bf16x2(v.x, v.y);
            uint32_t h1 = pack_bf16x2(v.z, v.w);
            uint32_t l0 = pack_bf16x2(v.x - bf_lo(h0), v.y - bf_hi(h0));
            uint32_t l1 = pack_bf16x2(v.z - bf_lo(h1), v.w - bf_hi(h1));

            // xor1 bfly: even j keeps word0 (pairA), sends word1;
            // odd j keeps word1 (pairB), sends word0.
            uint32_t hSend = oddj ? h0 : h1;
            uint32_t lSend = oddj ? l0 : l1;
            uint32_t hRecv = __shfl_xor_sync(0xffffffffu, hSend, 1);
            uint32_t lRecv = __shfl_xor_sync(0xffffffffu, lSend, 1);
            uint32_t hKeep = oddj ? h1 : h0;
            uint32_t lKeep = oddj ? l1 : l0;
            uint32_t hA = oddj ? hRecv : hKeep;   // fragment pair j   (a0/a1)
            uint32_t hB = oddj ? hKeep : hRecv;   // fragment pair j+4 (a2/a3)
            uint32_t lA = oddj ? lRecv : lKeep;
            uint32_t lB = oddj ? lKeep : lRecv;

            const int mt = o >> 1;
            const int hi8 = o & 1;                // row+8 slot?
            ah[mt][0 + hi8] = hA;
            ah[mt][2 + hi8] = hB;
            al[mt][0 + hi8] = lA;
            al[mt][2 + hi8] = lB;
        }

        const int bslot = s * 8 + 2 * j4;
#pragma unroll
        for (int t = 0; t < 8; t++) {
            const int nb = (wn * 64 + t * 8 + (lane >> 2)) * BSTRIDE;
            uint2 bhv = *(const uint2*)(Bh + nb + bslot);
            uint2 blv = *(const uint2*)(Bl + nb + bslot);
#pragma unroll
            for (int mt = 0; mt < 2; mt++) {
                mma16816(acc[mt][t], ah[mt][0], ah[mt][1], ah[mt][2], ah[mt][3], bhv.x, bhv.y);
                mma16816(acc[mt][t], al[mt][0], al[mt][1], al[mt][2], al[mt][3], bhv.x, bhv.y);
                mma16816(acc[mt][t], ah[mt][0], ah[mt][1], ah[mt][2], ah[mt][3], blv.x, blv.y);
            }
        }
    }

    // ---- quad reduce across the 4 lanes sharing each row ----
    if (wn == 0) {
#pragma unroll
        for (int o = 0; o < 4; o++) {
            q[o] += __shfl_xor_sync(0xffffffffu, q[o], 1);
            q[o] += __shfl_xor_sync(0xffffffffu, q[o], 2);
        }
        if (j4 == 0) {
            const int r = wm * 32 + (lane >> 2);
#pragma unroll
            for (int o = 0; o < 4; o++) qrow[r + 8 * o] = q[o];
        }
    }

    // ---- mu epilogue: direct float2 stores ----
    {
        float* om = out_mu + (size_t)rb * 128;
#pragma unroll
        for (int mt = 0; mt < 2; mt++) {
#pragma unroll
            for (int t = 0; t < 8; t++) {
                const int c = wn * 64 + t * 8 + 2 * j4;
                float2 bm = *(const float2*)(bmu + c);
                *(float2*)(om + (size_t)(mt * 16) * 128 + c) =
                    make_float2(acc[mt][t][0] + bm.x, acc[mt][t][1] + bm.y);
                *(float2*)(om + (size_t)(mt * 16 + 8) * 128 + c) =
                    make_float2(acc[mt][t][2] + bm.x, acc[mt][t][3] + bm.y);
            }
        }
    }

    __syncthreads();

    // ---- sigma output (coalesced float4) ----
    {
        float* osig = out_sigma + (size_t)blockIdx.x * (TILE_M * 128);
#pragma unroll
        for (int j = 0; j < 16; j++) {
            const int idx = j * NTHREADS + tid;
            const int row = idx >> 5;
            const int c   = (idx & 31) << 2;
            const float qv = qrow[row];
            float4 sp = *(const float4*)(spb + c);
            *(float4*)(osig + row * 128 + c) =
                make_float4(qv + sp.x, qv + sp.y, qv + sp.z, qv + sp.w);
        }
    }

    // ---- KL scalar (block 0 only) ----
    if (blockIdx.x == 0) {
        float s = 0.f;
        for (int i = tid; i < 16384; i += NTHREADS) s += fabsf(w_mu[i]);
#pragma unroll
        for (int o = 16; o; o >>= 1) s += __shfl_xor_sync(0xffffffffu, s, o);

        float r = 0.f;
        if (tid < 128) {
            float sw = spw[tid];
            r = logf(sw) - sw;
        }
#pragma unroll
        for (int o = 16; o; o >>= 1) r += __shfl_xor_sync(0xffffffffu, r, o);

        if (lane == 0) { red[warp] = s; red[8 + warp] = r; }
        __syncthreads();
        if (tid == 0) {
            float S = 0.f, R = 0.f;
            for (int w2 = 0; w2 < 8; w2++) { S += red[w2]; R += red[8 + w2]; }
            out_kl[0] = -0.5f * (R - S);
        }
    }
}

// ---------------------------------------------------------------------------
extern "C" void kernel_launch(void* const* d_in, const int* in_sizes, int n_in,
                              void* d_out, int out_size) {
    const float* x       = (const float*)d_in[0];
    const float* w_mu    = (const float*)d_in[1];
    const float* w_sigma = (const float*)d_in[2];
    const float* b_mu    = (const float*)d_in[3];
    const float* b_sigma = (const float*)d_in[4];

    const int batch = in_sizes[0] / 128;
    float* out       = (float*)d_out;
    float* out_mu    = out;
    float* out_sigma = out + (size_t)batch * 128;
    float* out_kl    = out + (size_t)batch * 256;

    cudaFuncSetAttribute(rvlinear_kernel,
                         cudaFuncAttributeMaxDynamicSharedMemorySize, SMEM_TOTAL);
    rvlinear_kernel<<<batch / TILE_M, NTHREADS, SMEM_TOTAL>>>(
        x, w_mu, w_sigma, b_mu, b_sigma, out_mu, out_sigma, out_kl);
}

// round 13
// speedup vs baseline: 1.1430x; 1.1430x over previous
#include <cuda_runtime.h>
#include <cuda_bf16.h>
#include <cstdint>

// ---------------------------------------------------------------------------
// Fused RV-linear layer (HMMA mma.sync path).
// R13 = R4 (proven 226us: 4x2 warp grid, 32x64 warp tile, direct LDG.64 A
// fragments) + s-loop unrolled by 2 so ptxas can software-pipeline the
// x loads of iteration s+1 under the MMA block of iteration s.
// ---------------------------------------------------------------------------

#define NTHREADS 256
#define TILE_M   128

// ---- dynamic shared memory layout (bytes) ----
#define SM_QROW  0                 // 128 floats
#define SM_SPW   512               // 128 floats
#define SM_SPB   1024
#define SM_BMU   1536
#define SM_RED   2048              // 16 floats
#define SM_BH    2112              // 128*68 uint32 = 34816 B (bf16x2 k-pairs, hi)
#define SM_BL    (2112 + 34816)    // same, lo
#define SMEM_TOTAL (SM_BL + 34816) // 71744 B
#define BSTRIDE  68                // 68 % 32 == 4 -> (4*n + p) banks, conflict-free

__device__ __forceinline__ uint32_t pack_bf16x2(float lo, float hi) {
    uint32_t r;
    asm("cvt.rn.bf16x2.f32 %0, %1, %2;" : "=r"(r) : "f"(hi), "f"(lo));
    return r;
}
__device__ __forceinline__ float bf_lo(uint32_t u) { return __uint_as_float(u << 16); }
__device__ __forceinline__ float bf_hi(uint32_t u) { return __uint_as_float(u & 0xffff0000u); }

__device__ __forceinline__ void mma16816(float* d, uint32_t a0, uint32_t a1,
                                         uint32_t a2, uint32_t a3,
                                         uint32_t b0, uint32_t b1) {
    asm volatile(
        "mma.sync.aligned.m16n8k16.row.col.f32.bf16.bf16.f32 "
        "{%0,%1,%2,%3}, {%4,%5,%6,%7}, {%8,%9}, {%0,%1,%2,%3};"
        : "+f"(d[0]), "+f"(d[1]), "+f"(d[2]), "+f"(d[3])
        : "r"(a0), "r"(a1), "r"(a2), "r"(a3), "r"(b0), "r"(b1));
}

// ---------------------------------------------------------------------------
__global__ void __launch_bounds__(NTHREADS, 2)
rvlinear_kernel(const float* __restrict__ x,
                const float* __restrict__ w_mu,
                const float* __restrict__ w_sigma,
                const float* __restrict__ b_mu,
                const float* __restrict__ b_sigma,
                float* __restrict__ out_mu,
                float* __restrict__ out_sigma,
                float* __restrict__ out_kl) {
    extern __shared__ __align__(16) char smem[];
    float*    qrow = (float*)(smem + SM_QROW);
    float*    spw  = (float*)(smem + SM_SPW);
    float*    spb  = (float*)(smem + SM_SPB);
    float*    bmu  = (float*)(smem + SM_BMU);
    float*    red  = (float*)(smem + SM_RED);
    uint32_t* Bh   = (uint32_t*)(smem + SM_BH);
    uint32_t* Bl   = (uint32_t*)(smem + SM_BL);

    const int tid  = threadIdx.x;
    const int warp = tid >> 5;
    const int lane = tid & 31;

    if (tid < 128) {
        spw[tid] = log1pf(expf(w_sigma[tid]));
        spb[tid] = log1pf(expf(b_sigma[tid]));
        bmu[tid] = b_mu[tid];
    }

    // ---- build B = w_mu^T as bf16x2 (k-pair) hi/lo in SMEM ----
    {
        const int nsub = lane & 7;                 // 0..7
        const int psub = lane >> 3;                // 0..3
        const int n4b  = nsub + 8 * (warp & 3);    // 0..31
        const int pb   = psub + 4 * (warp >> 2);   // 0..7
#pragma unroll
        for (int j = 0; j < 8; j++) {
            const int p  = pb + 8 * j;             // kpair 0..63
            const int n0 = 4 * n4b;
            float4 w0 = *(const float4*)(w_mu + (2 * p) * 128 + n0);
            float4 w1 = *(const float4*)(w_mu + (2 * p + 1) * 128 + n0);
            float a[4] = {w0.x, w0.y, w0.z, w0.w};
            float b[4] = {w1.x, w1.y, w1.z, w1.w};
#pragma unroll
            for (int dn = 0; dn < 4; dn++) {
                uint32_t h = pack_bf16x2(a[dn], b[dn]);
                uint32_t l = pack_bf16x2(a[dn] - bf_lo(h), b[dn] - bf_hi(h));
                const int n = n0 + dn;
                Bh[n * BSTRIDE + p] = h;
                Bl[n * BSTRIDE + p] = l;
            }
        }
    }
    __syncthreads();

    // ---- main GEMM: 4x2 warp grid; warp tile = 32 rows x 64 cols ----
    const int wm = warp & 3;       // M group (32 rows)
    const int wn = warp >> 2;      // N half (64 cols)
    const int rb = blockIdx.x * TILE_M + wm * 32 + (lane >> 2);
    const float* xr = x + (size_t)rb * 128;

    float acc[2][8][4];
#pragma unroll
    for (int mt = 0; mt < 2; mt++)
#pragma unroll
        for (int t = 0; t < 8; t++) {
            acc[mt][t][0] = 0.f; acc[mt][t][1] = 0.f;
            acc[mt][t][2] = 0.f; acc[mt][t][3] = 0.f;
        }

    float q[4] = {0.f, 0.f, 0.f, 0.f};   // quad partials for rows rb+{0,8,16,24}

#pragma unroll 2
    for (int s = 0; s < 8; s++) {
        const int c0 = 16 * s + 2 * (lane & 3);
        float2 xv[4][2];
#pragma unroll
        for (int o = 0; o < 4; o++) {
            xv[o][0] = *(const float2*)(xr + (size_t)(8 * o) * 128 + c0);
            xv[o][1] = *(const float2*)(xr + (size_t)(8 * o) * 128 + c0 + 8);
        }

        if (wn == 0) {
            float2 sa = *(const float2*)(spw + c0);
            float2 sb2 = *(const float2*)(spw + c0 + 8);
#pragma unroll
            for (int o = 0; o < 4; o++) {
                q[o] += xv[o][0].x * xv[o][0].x * sa.x
                      + xv[o][0].y * xv[o][0].y * sa.y
                      + xv[o][1].x * xv[o][1].x * sb2.x
                      + xv[o][1].y * xv[o][1].y * sb2.y;
            }
        }

        // hi/lo split: a-frag words per m-tile [a0,a1,a2,a3]
        uint32_t ah[2][4], al[2][4];
#pragma unroll
        for (int mt = 0; mt < 2; mt++) {
            const int o0 = 2 * mt, o1 = 2 * mt + 1;
            ah[mt][0] = pack_bf16x2(xv[o0][0].x, xv[o0][0].y);
            ah[mt][1] = pack_bf16x2(xv[o1][0].x, xv[o1][0].y);
            ah[mt][2] = pack_bf16x2(xv[o0][1].x, xv[o0][1].y);
            ah[mt][3] = pack_bf16x2(xv[o1][1].x, xv[o1][1].y);
            al[mt][0] = pack_bf16x2(xv[o0][0].x - bf_lo(ah[mt][0]),
                                    xv[o0][0].y - bf_hi(ah[mt][0]));
            al[mt][1] = pack_bf16x2(xv[o1][0].x - bf_lo(ah[mt][1]),
                                    xv[o1][0].y - bf_hi(ah[mt][1]));
            al[mt][2] = pack_bf16x2(xv[o0][1].x - bf_lo(ah[mt][2]),
                                    xv[o0][1].y - bf_hi(ah[mt][2]));
            al[mt][3] = pack_bf16x2(xv[o1][1].x - bf_lo(ah[mt][3]),
                                    xv[o1][1].y - bf_hi(ah[mt][3]));
        }

        const int prow = 8 * s + (lane & 3);
#pragma unroll
        for (int t = 0; t < 8; t++) {
            const int nb = (wn * 64 + t * 8 + (lane >> 2)) * BSTRIDE;
            uint32_t bh0 = Bh[nb + prow];
            uint32_t bh1 = Bh[nb + prow + 4];
            uint32_t bl0 = Bl[nb + prow];
            uint32_t bl1 = Bl[nb + prow + 4];
#pragma unroll
            for (int mt = 0; mt < 2; mt++) {
                mma16816(acc[mt][t], ah[mt][0], ah[mt][1], ah[mt][2], ah[mt][3], bh0, bh1);
                mma16816(acc[mt][t], al[mt][0], al[mt][1], al[mt][2], al[mt][3], bh0, bh1);
                mma16816(acc[mt][t], ah[mt][0], ah[mt][1], ah[mt][2], ah[mt][3], bl0, bl1);
            }
        }
    }

    // ---- quad reduce across the 4 lanes sharing each row ----
    if (wn == 0) {
#pragma unroll
        for (int o = 0; o < 4; o++) {
            q[o] += __shfl_xor_sync(0xffffffffu, q[o], 1);
            q[o] += __shfl_xor_sync(0xffffffffu, q[o], 2);
        }
        if ((lane & 3) == 0) {
            const int r = wm * 32 + (lane >> 2);
#pragma unroll
            for (int o = 0; o < 4; o++) qrow[r + 8 * o] = q[o];
        }
    }

    // ---- mu epilogue: direct float2 stores ----
    {
        float* om = out_mu + (size_t)rb * 128;
#pragma unroll
        for (int mt = 0; mt < 2; mt++) {
#pragma unroll
            for (int t = 0; t < 8; t++) {
                const int c = wn * 64 + t * 8 + 2 * (lane & 3);
                float2 bm = *(const float2*)(bmu + c);
                *(float2*)(om + (size_t)(mt * 16) * 128 + c) =
                    make_float2(acc[mt][t][0] + bm.x, acc[mt][t][1] + bm.y);
                *(float2*)(om + (size_t)(mt * 16 + 8) * 128 + c) =
                    make_float2(acc[mt][t][2] + bm.x, acc[mt][t][3] + bm.y);
            }
        }
    }

    __syncthreads();

    // ---- sigma output (coalesced float4) ----
    {
        float* osig = out_sigma + (size_t)blockIdx.x * (TILE_M * 128);
#pragma unroll
        for (int j = 0; j < 16; j++) {
            const int idx = j * NTHREADS + tid;
            const int row = idx >> 5;
            const int c   = (idx & 31) << 2;
            const float qv = qrow[row];
            float4 sp = *(const float4*)(spb + c);
            *(float4*)(osig + row * 128 + c) =
                make_float4(qv + sp.x, qv + sp.y, qv + sp.z, qv + sp.w);
        }
    }

    // ---- KL scalar (block 0 only) ----
    if (blockIdx.x == 0) {
        float s = 0.f;
        for (int i = tid; i < 16384; i += NTHREADS) s += fabsf(w_mu[i]);
#pragma unroll
        for (int o = 16; o; o >>= 1) s += __shfl_xor_sync(0xffffffffu, s, o);

        float r = 0.f;
        if (tid < 128) {
            float sw = spw[tid];
            r = logf(sw) - sw;
        }
#pragma unroll
        for (int o = 16; o; o >>= 1) r += __shfl_xor_sync(0xffffffffu, r, o);

        if (lane == 0) { red[warp] = s; red[8 + warp] = r; }
        __syncthreads();
        if (tid == 0) {
            float S = 0.f, R = 0.f;
            for (int w2 = 0; w2 < 8; w2++) { S += red[w2]; R += red[8 + w2]; }
            out_kl[0] = -0.5f * (R - S);
        }
    }
}

// ---------------------------------------------------------------------------
extern "C" void kernel_launch(void* const* d_in, const int* in_sizes, int n_in,
                              void* d_out, int out_size) {
    const float* x       = (const float*)d_in[0];
    const float* w_mu    = (const float*)d_in[1];
    const float* w_sigma = (const float*)d_in[2];
    const float* b_mu    = (const float*)d_in[3];
    const float* b_sigma = (const float*)d_in[4];

    const int batch = in_sizes[0] / 128;
    float* out       = (float*)d_out;
    float* out_mu    = out;
    float* out_sigma = out + (size_t)batch * 128;
    float* out_kl    = out + (size_t)batch * 256;

    cudaFuncSetAttribute(rvlinear_kernel,
                         cudaFuncAttributeMaxDynamicSharedMemorySize, SMEM_TOTAL);
    rvlinear_kernel<<<batch / TILE_M, NTHREADS, SMEM_TOTAL>>>(
        x, w_mu, w_sigma, b_mu, b_sigma, out_mu, out_sigma, out_kl);
}